// round 13
// baseline (speedup 1.0000x reference)
#include <cuda_runtime.h>
#include <cuda_bf16.h>
#include <math.h>
#include <stdint.h>

#define TT 256
#define BB 128
#define HH 1024
#define DD 1024
#define BH (BB*HH)
#define NG 4096       // 4 gates * 1024
#define KSPLIT 4

// ---------------- device global scratch (no allocs allowed) ----------------
static __device__ float g_Z[(size_t)TT*BB*NG];
static __device__ float g_P[(size_t)KSPLIT*BB*NG];
static __device__ float g_zero[HH];
static __device__ float g_bias[NG];
static __device__ float g_ws[NG];                    // per-row combined scale sw/127
static __device__ unsigned g_barcnt;
static __device__ __align__(16) __nv_bfloat16 g_Xhi[(size_t)TT*BB*DD];
static __device__ __align__(16) __nv_bfloat16 g_Xlo[(size_t)TT*BB*DD];
static __device__ __align__(16) __nv_bfloat16 g_Wxhi[(size_t)NG*HH];
static __device__ __align__(16) __nv_bfloat16 g_Wxlo[(size_t)NG*HH];
static __device__ __align__(16) char g_Wh1[(size_t)NG*HH];   // int8 weight planes (recurrent)
static __device__ __align__(16) char g_Wh2[(size_t)NG*HH];
static __device__ __align__(16) char g_h1[BH];               // int8 hidden planes
static __device__ __align__(16) char g_h2[BH];

// ---------------- PTX helpers (baseline ISA only) ----------------
__device__ __forceinline__ uint32_t smem_u32(const void* p){
    uint32_t a;
    asm("{ .reg .u64 t; cvta.to.shared.u64 t, %1; cvt.u32.u64 %0, t; }" : "=r"(a) : "l"(p));
    return a;
}
__device__ __forceinline__ void ldsm4(uint32_t& r0, uint32_t& r1, uint32_t& r2, uint32_t& r3, uint32_t a){
    asm volatile("ldmatrix.sync.aligned.m8n8.x4.shared.b16 {%0,%1,%2,%3}, [%4];"
                 : "=r"(r0), "=r"(r1), "=r"(r2), "=r"(r3) : "r"(a));
}
__device__ __forceinline__ void mma16816(float* d, const uint32_t* a, const uint32_t* b){
    asm volatile("mma.sync.aligned.m16n8k16.row.col.f32.bf16.bf16.f32 "
                 "{%0,%1,%2,%3}, {%4,%5,%6,%7}, {%8,%9}, {%0,%1,%2,%3};"
                 : "+f"(d[0]), "+f"(d[1]), "+f"(d[2]), "+f"(d[3])
                 : "r"(a[0]), "r"(a[1]), "r"(a[2]), "r"(a[3]), "r"(b[0]), "r"(b[1]));
}
// s8 MMA: m16n8k32, s32 accum. Fragment byte-layout identical to bf16 m16n8k16.
__device__ __forceinline__ void mmai8(int* d, const uint32_t* a, const uint32_t* b){
    asm volatile("mma.sync.aligned.m16n8k32.row.col.s32.s8.s8.s32 "
                 "{%0,%1,%2,%3}, {%4,%5,%6,%7}, {%8,%9}, {%0,%1,%2,%3};"
                 : "+r"(d[0]), "+r"(d[1]), "+r"(d[2]), "+r"(d[3])
                 : "r"(a[0]), "r"(a[1]), "r"(a[2]), "r"(a[3]), "r"(b[0]), "r"(b[1]));
}
__device__ __forceinline__ void cpa16(uint32_t dst, const void* src){
    asm volatile("cp.async.cg.shared.global [%0], [%1], 16;" :: "r"(dst), "l"(src));
}
#define CP_COMMIT asm volatile("cp.async.commit_group;" ::: "memory")
#define CP_WAIT1  asm volatile("cp.async.wait_group 1;" ::: "memory")
#define CP_WAIT0  asm volatile("cp.async.wait_group 0;" ::: "memory")

__device__ __forceinline__ float fsig(float x){ return 1.f/(1.f + __expf(-x)); }
__device__ __forceinline__ float ftanh(float x){ return 1.f - 2.f/(__expf(2.f*x) + 1.f); }
__device__ __forceinline__ int clamp127(int v){ return v < -127 ? -127 : (v > 127 ? 127 : v); }

// ---------------- init ----------------
__global__ void k_init(const float* __restrict__ bf, const float* __restrict__ bi,
                       const float* __restrict__ bu, const float* __restrict__ bo){
    int i = blockIdx.x*256 + threadIdx.x;      // grid covers BH
    g_h1[i] = 0; g_h2[i] = 0;
    if (i < HH) g_zero[i] = 0.f;
    if (i < NG){
        int g = i >> 10, n = i & 1023;
        g_bias[i] = (g==0?bf:g==1?bi:g==2?bu:bo)[n];
    }
    if (i == 0) g_barcnt = 0u;
}

// ---------------- fp32 -> bf16 hi/lo split ----------------
__device__ __forceinline__ void split4(float4 a, uint2& hi, uint2& lo){
    union { __nv_bfloat16 b[4]; uint2 u; } H, L;
    float x[4] = {a.x, a.y, a.z, a.w};
    #pragma unroll
    for (int j=0;j<4;j++){
        __nv_bfloat16 h = __float2bfloat16(x[j]);
        H.b[j] = h;
        L.b[j] = __float2bfloat16(x[j] - __bfloat162float(h));
    }
    hi = H.u; lo = L.u;
}

__global__ __launch_bounds__(256) void k_cvtX(const float* __restrict__ X){
    size_t v = (size_t)blockIdx.x*256 + threadIdx.x;
    float4 a = *(const float4*)(X + v*4);
    uint2 hi, lo; split4(a, hi, lo);
    *(uint2*)((char*)g_Xhi + v*8) = hi;
    *(uint2*)((char*)g_Xlo + v*8) = lo;
}

// Wx (input-projection half) -> bf16 hi/lo  (k_pre operand; unchanged path)
__global__ __launch_bounds__(256) void k_cvtW(const float* __restrict__ Wf, const float* __restrict__ Wi,
                                              const float* __restrict__ Wu, const float* __restrict__ Wo){
    int g = blockIdx.y;
    const float* __restrict__ W = (g==0)?Wf:(g==1)?Wi:(g==2)?Wu:Wo;
    int v = blockIdx.x*256 + threadIdx.x;
    int n  = v >> 8;
    int kv = (v & 255) * 4;
    size_t o = ((size_t)g*1024 + n)*1024 + kv;
    float4 ax = *(const float4*)(W + (size_t)n*2048 + kv);
    uint2 hi, lo;
    split4(ax, hi, lo);
    *(uint2*)((char*)g_Wxhi + o*2) = hi;
    *(uint2*)((char*)g_Wxlo + o*2) = lo;
}

// Wh (recurrent half) -> int8 two-plane split with per-row scale.
// One block per output row n (4096 blocks).
__global__ __launch_bounds__(256) void k_cvtWh(const float* __restrict__ Wf, const float* __restrict__ Wi,
                                               const float* __restrict__ Wu, const float* __restrict__ Wo){
    __shared__ float red[8];
    __shared__ float s_sw;
    const int n = blockIdx.x;
    const int g = n >> 10, r = n & 1023;
    const float* __restrict__ W = ((g==0)?Wf:(g==1)?Wi:(g==2)?Wu:Wo) + (size_t)r*2048 + 1024;
    const int tid = threadIdx.x;
    const int lane = tid & 31;

    float mx = 0.f;
    #pragma unroll
    for (int j=0;j<4;j++) mx = fmaxf(mx, fabsf(W[tid + j*256]));
    #pragma unroll
    for (int o=16;o;o>>=1) mx = fmaxf(mx, __shfl_xor_sync(0xFFFFFFFFu, mx, o));
    if (lane == 0) red[tid >> 5] = mx;
    __syncthreads();
    if (tid == 0){
        float m = red[0];
        #pragma unroll
        for (int w=1; w<8; w++) m = fmaxf(m, red[w]);
        float sw = fmaxf(m, 1e-30f) / 127.f;
        s_sw = sw;
        g_ws[n] = sw / 127.f;        // combined scale: P = (d1 + d12/256) * g_ws
    }
    __syncthreads();
    const float inv = 1.f / s_sw;
    #pragma unroll
    for (int j=0;j<4;j++){
        int k = tid + j*256;
        float q = W[k] * inv;                 // |q| <= 127
        int w1 = clamp127(__float2int_rn(q));
        int w2 = clamp127(__float2int_rn((q - (float)w1) * 256.f));
        g_Wh1[(size_t)n*1024 + k] = (char)w1;
        g_Wh2[(size_t)n*1024 + k] = (char)w2;
    }
}

// ---------------- precompute GEMM (R6/R12-proven: tensor=74%) ----------
__global__ __launch_bounds__(256, 2) void k_pre(){
    extern __shared__ char smem[];
    const uint32_t sbase = smem_u32(smem);
    const int tid  = threadIdx.x;
    const int lane = tid & 31;
    const int wid  = tid >> 5;
    const int wm   = wid >> 1;
    const int wn   = wid & 1;
    const int n0   = blockIdx.x * 128;
    const int y    = blockIdx.y;

    const __nv_bfloat16* Ah = g_Xhi + (size_t)y*131072;
    const __nv_bfloat16* Al = g_Xlo + (size_t)y*131072;
    const __nv_bfloat16* Bh = g_Wxhi + (size_t)n0*1024;
    const __nv_bfloat16* Bl = g_Wxlo + (size_t)n0*1024;
    float* out = g_Z + (size_t)y*BB*NG;

    float acc[2][8][4];
    #pragma unroll
    for (int i=0;i<2;i++)
        #pragma unroll
        for (int j=0;j<8;j++)
            #pragma unroll
            for (int q=0;q<4;q++) acc[i][j][q] = 0.f;

    int lrow[2], ldst[2], lgc[2];
    #pragma unroll
    for (int i=0;i<2;i++){
        int ch = tid + i*256;
        int r = ch >> 2, c = ch & 3;
        lrow[i] = r; lgc[i] = c*8;
        ldst[i] = r*64 + ((c ^ ((r>>1)&3))<<4);
    }

    #define LOAD_SLAB(stg, ks) do {                                   \
        uint32_t sb_ = sbase + (stg)*32768;                            \
        _Pragma("unroll")                                              \
        for (int i_=0;i_<2;i_++){                                      \
            size_t go_ = (size_t)lrow[i_]*1024 + (ks) + lgc[i_];       \
            cpa16(sb_ + ldst[i_],          Ah + go_);                  \
            cpa16(sb_ + 8192  + ldst[i_],  Al + go_);                  \
            cpa16(sb_ + 16384 + ldst[i_],  Bh + go_);                  \
            cpa16(sb_ + 24576 + ldst[i_],  Bl + go_);                  \
        }                                                              \
    } while(0)

    LOAD_SLAB(0, 0);
    CP_COMMIT;

    for (int s = 0; s < 32; s++){
        if (s+1 < 32){ LOAD_SLAB((s+1)&1, (s+1)*32); CP_COMMIT; CP_WAIT1; }
        else CP_WAIT0;
        __syncthreads();

        const uint32_t sA = sbase + (s&1)*32768;
        const uint32_t sB = sA + 16384;
        #pragma unroll
        for (int kk = 0; kk < 2; kk++){
            uint32_t ah[2][4], al[2][4];
            #pragma unroll
            for (int mt=0; mt<2; mt++){
                int r = wm*32 + mt*16 + (lane & 15);
                int c = kk*2 + (lane >> 4);
                uint32_t ad = sA + r*64 + (((c ^ ((r>>1)&3)))<<4);
                ldsm4(ah[mt][0], ah[mt][1], ah[mt][2], ah[mt][3], ad);
                ldsm4(al[mt][0], al[mt][1], al[mt][2], al[mt][3], ad + 8192);
            }
            #pragma unroll
            for (int ntp=0; ntp<4; ntp++){
                int q = lane >> 3;
                int n = wn*64 + ntp*16 + ((q>>1)<<3) + (lane & 7);
                int kc = kk*2 + (q & 1);
                uint32_t bd = sB + n*64 + (((kc ^ ((n>>1)&3)))<<4);
                uint32_t bh[4], bl[4];
                ldsm4(bh[0], bh[1], bh[2], bh[3], bd);
                ldsm4(bl[0], bl[1], bl[2], bl[3], bd + 8192);
                #pragma unroll
                for (int mt=0; mt<2; mt++){
                    mma16816(acc[mt][2*ntp],   ah[mt], bh);
                    mma16816(acc[mt][2*ntp],   ah[mt], bl);
                    mma16816(acc[mt][2*ntp],   al[mt], bh);
                    mma16816(acc[mt][2*ntp+1], ah[mt], bh+2);
                    mma16816(acc[mt][2*ntp+1], ah[mt], bl+2);
                    mma16816(acc[mt][2*ntp+1], al[mt], bh+2);
                }
            }
        }
        __syncthreads();
    }
    #undef LOAD_SLAB

    #pragma unroll
    for (int mt=0; mt<2; mt++){
        int m = wm*32 + mt*16 + (lane >> 2);
        #pragma unroll
        for (int nt=0; nt<8; nt++){
            int nc = n0 + wn*64 + nt*8 + (lane & 3)*2;
            float b0 = g_bias[nc], b1 = g_bias[nc+1];
            float2 v0 = make_float2(acc[mt][nt][0] + b0, acc[mt][nt][1] + b1);
            float2 v1 = make_float2(acc[mt][nt][2] + b0, acc[mt][nt][3] + b1);
            *(float2*)(out + (size_t)m*NG + nc)     = v0;
            *(float2*)(out + (size_t)(m+8)*NG + nc) = v1;
        }
    }
}

// ---------------- persistent recurrent kernel: int8 split GEMM --------------
// Smem: W1 [4 x 8KB] @0 | W2 @32K | A 3-stage @64K (3 x 16KB: A1+A2) |
//       sW tile @112K (512B) | pf @112.5K (24KB)
#define ASTAGE_OFF 65536
#define SWS_OFF    114688
#define PF_OFF     115200
__global__ __launch_bounds__(512) void k_loop(const float* __restrict__ X,
                                              float* __restrict__ out){
    extern __shared__ char smem[];
    __shared__ float red[16];
    const uint32_t sbase = smem_u32(smem);
    const int tid  = threadIdx.x;
    const int lane = tid & 31;
    const int wid  = tid >> 5;
    const int wm   = wid & 3;      // M group: 4 x 32 rows
    const int wn   = wid >> 2;     // N group: 4 x 32 cols
    const int bid  = blockIdx.x;
    const int nt   = bid & 31;
    const int ks   = bid >> 5;
    const int n0   = nt * 128;
    const int b    = bid;

    // load geometry: 64B rows, 4 x 16B chunks, xor swizzle (identical to bf16 path)
    const int lrow = tid >> 2, lch = tid & 3;
    const uint32_t ldst = lrow*64 + ((lch ^ ((lrow>>1)&3))<<4);
    const int lgc = lch*16;                 // 16 int8 per chunk

    // ---- resident int8 weights (once): 4 slabs x (W1 8KB + W2 8KB) ----
    {
        const char* W1 = g_Wh1 + (size_t)n0*1024 + ks*256;
        const char* W2 = g_Wh2 + (size_t)n0*1024 + ks*256;
        #pragma unroll
        for (int s=0; s<4; s++){
            size_t go = (size_t)lrow*1024 + s*64 + lgc;
            cpa16(sbase + s*8192 + ldst,         W1 + go);
            cpa16(sbase + 32768 + s*8192 + ldst, W2 + go);
        }
        CP_COMMIT; CP_WAIT0;
        if (tid < 128) *(float*)(smem + SWS_OFF + tid*4) = g_ws[n0 + tid];
        __syncthreads();
    }

    const uint32_t sAbase = sbase + ASTAGE_OFF;
    const char* A1 = g_h1 + ks*256;
    const char* A2 = g_h2 + ks*256;
    float* Pout = g_P + (size_t)ks*BB*NG + n0;
    const char* smc = smem;
    const float* sws  = (const float*)(smc + SWS_OFF);
    const float* xsp  = (const float*)(smc + PF_OFF);
    const float* hpsp = (const float*)(smc + PF_OFF + 4096);
    const float* Zsp  = (const float*)(smc + PF_OFF + 8192);

    float2 creg = make_float2(0.f, 0.f);   // cell state, units 2*tid, 2*tid+1

    #define LOAD_A(stg, s_) do {                                        \
        uint32_t sb_ = sAbase + (stg)*16384;                             \
        size_t go_ = (size_t)lrow*1024 + (s_)*64 + lgc;                  \
        cpa16(sb_ + ldst,        A1 + go_);                              \
        cpa16(sb_ + 8192 + ldst, A2 + go_);                              \
    } while(0)

    for (int t = 0; t < TT; t++){
        // ---- prefetch x, h_prev, Z (1536 16B-chunks over 512 threads) ----
        {
            const float* xr = X + ((size_t)t*BB + b)*DD;
            const float* hp = t ? (out + ((size_t)(t-1)*BB + b)*HH) : g_zero;
            const float* Zr = g_Z + ((size_t)t*BB + b)*NG;
            #pragma unroll
            for (int i=0;i<3;i++){
                int cidx = tid + i*512;
                if (cidx < 256)       cpa16(sbase + PF_OFF + cidx*16, xr + cidx*4);
                else if (cidx < 512)  cpa16(sbase + PF_OFF + 4096 + (cidx-256)*16, hp + (cidx-256)*4);
                else                  cpa16(sbase + PF_OFF + 8192 + (cidx-512)*16, Zr + (cidx-512)*4);
            }
        }

        // ======== GEMM phase: int8 split, 4 slabs of BK=64 int8, 3-stage ========
        int d1[2][4][4], d12[2][4][4];
        #pragma unroll
        for (int i=0;i<2;i++)
            #pragma unroll
            for (int j=0;j<4;j++)
                #pragma unroll
                for (int q=0;q<4;q++){ d1[i][j][q] = 0; d12[i][j][q] = 0; }

        LOAD_A(0, 0); CP_COMMIT;   // g0: prefetch + slab0
        LOAD_A(1, 1); CP_COMMIT;   // g1: slab1
        for (int s = 0; s < 4; s++){
            if (s < 3) CP_WAIT1; else CP_WAIT0;
            __syncthreads();
            if (s + 2 < 4){ LOAD_A((s+2)%3, s+2); CP_COMMIT; }

            const uint32_t sA  = sAbase + (s%3)*16384;
            const uint32_t sBh = sbase + s*8192;
            #pragma unroll
            for (int kk = 0; kk < 2; kk++){   // two k32 chunks per slab
                uint32_t a1[2][4], a2[2][4], b1[2][4], b2[2][4];
                #pragma unroll
                for (int mt=0; mt<2; mt++){
                    int r = wm*32 + mt*16 + (lane & 15);
                    int c = kk*2 + (lane >> 4);
                    uint32_t ad = sA + r*64 + (((c ^ ((r>>1)&3)))<<4);
                    ldsm4(a1[mt][0], a1[mt][1], a1[mt][2], a1[mt][3], ad);
                    ldsm4(a2[mt][0], a2[mt][1], a2[mt][2], a2[mt][3], ad + 8192);
                }
                #pragma unroll
                for (int ntp=0; ntp<2; ntp++){
                    int q = lane >> 3;
                    int n = wn*32 + ntp*16 + ((q>>1)<<3) + (lane & 7);
                    int kc = kk*2 + (q & 1);
                    uint32_t bd = sBh + n*64 + (((kc ^ ((n>>1)&3)))<<4);
                    ldsm4(b1[ntp][0], b1[ntp][1], b1[ntp][2], b1[ntp][3], bd);
                    ldsm4(b2[ntp][0], b2[ntp][1], b2[ntp][2], b2[ntp][3], bd + 32768);
                }
                // term-ordered: d1 += A1W1; d12 += A1W2; d12 += A2W1
                #pragma unroll
                for (int mt=0; mt<2; mt++)
                    #pragma unroll
                    for (int ntp=0; ntp<2; ntp++){
                        mmai8(d1[mt][2*ntp],   a1[mt], b1[ntp]);
                        mmai8(d1[mt][2*ntp+1], a1[mt], b1[ntp]+2);
                    }
                #pragma unroll
                for (int mt=0; mt<2; mt++)
                    #pragma unroll
                    for (int ntp=0; ntp<2; ntp++){
                        mmai8(d12[mt][2*ntp],   a1[mt], b2[ntp]);
                        mmai8(d12[mt][2*ntp+1], a1[mt], b2[ntp]+2);
                    }
                #pragma unroll
                for (int mt=0; mt<2; mt++)
                    #pragma unroll
                    for (int ntp=0; ntp<2; ntp++){
                        mmai8(d12[mt][2*ntp],   a2[mt], b1[ntp]);
                        mmai8(d12[mt][2*ntp+1], a2[mt], b1[ntp]+2);
                    }
            }
        }

        // epilogue: combine scales, write fp32 partials
        #pragma unroll
        for (int mt=0; mt<2; mt++){
            int m = wm*32 + mt*16 + (lane >> 2);
            #pragma unroll
            for (int j=0; j<4; j++){
                int nc = wn*32 + j*8 + (lane & 3)*2;
                float s0 = sws[nc], s1 = sws[nc+1];
                float p00 = ((float)d1[mt][j][0] + (float)d12[mt][j][0]*0.00390625f)*s0;
                float p01 = ((float)d1[mt][j][1] + (float)d12[mt][j][1]*0.00390625f)*s1;
                float p10 = ((float)d1[mt][j][2] + (float)d12[mt][j][2]*0.00390625f)*s0;
                float p11 = ((float)d1[mt][j][3] + (float)d12[mt][j][3]*0.00390625f)*s1;
                *(float2*)(Pout + (size_t)m*NG + nc)     = make_float2(p00, p01);
                *(float2*)(Pout + (size_t)(m+8)*NG + nc) = make_float2(p10, p11);
            }
        }

        // ---- RBF partial BEFORE barrier A (prefetched smem only) ----
        {
            const int n2 = 2*tid;
            float2 xv = *(const float2*)(xsp + n2);
            float2 hv = *(const float2*)(hpsp + n2);
            float dx0 = xv.x - hv.x, dx1 = xv.y - hv.y;
            float sacc = dx0*dx0 + dx1*dx1;
            #pragma unroll
            for (int o=16;o;o>>=1) sacc += __shfl_xor_sync(0xFFFFFFFFu, sacc, o);
            if (lane == 0) red[wid] = sacc;
        }

        // ---- grid barrier A ----
        __syncthreads();
        if (tid == 0){
            __threadfence();
            atomicAdd(&g_barcnt, 1u);
            unsigned tgt = 128u*(2u*t + 1u);
            while (*(volatile unsigned*)&g_barcnt < tgt) {}
        }
        __syncthreads();

        // ======== elementwise phase: batch row b, units 2*tid, 2*tid+1 ========
        {
            const int n2 = 2*tid;
            float tot = 0.f;
            #pragma unroll
            for (int w=0; w<16; w++) tot += red[w];
            const float kk_ = __expf(-tot);

            float2 pf = *(const float2*)(Zsp + n2);
            float2 pi = *(const float2*)(Zsp + 1024 + n2);
            float2 pu = *(const float2*)(Zsp + 2048 + n2);
            float2 po = *(const float2*)(Zsp + 3072 + n2);
            #pragma unroll
            for (int sp=0; sp<KSPLIT; sp++){
                const float* P = g_P + ((size_t)sp*BB + b)*NG;
                float2 a0 = __ldcg((const float2*)(P + n2));
                float2 a1 = __ldcg((const float2*)(P + 1024 + n2));
                float2 a2 = __ldcg((const float2*)(P + 2048 + n2));
                float2 a3 = __ldcg((const float2*)(P + 3072 + n2));
                pf.x += a0.x; pf.y += a0.y;
                pi.x += a1.x; pi.y += a1.y;
                pu.x += a2.x; pu.y += a2.y;
                po.x += a3.x; po.y += a3.y;
            }
            float f0 = fsig(pf.x + kk_), f1 = fsig(pf.y + kk_);
            float i0 = fsig(pi.x + kk_), i1 = fsig(pi.y + kk_);
            float u0 = ftanh(pu.x),      u1 = ftanh(pu.y);
            float o0 = fsig(po.x + kk_), o1 = fsig(po.y + kk_);
            creg.x = f0*creg.x + i0*u0;
            creg.y = f1*creg.y + i1*u1;
            float h0 = o0*ftanh(creg.x);
            float h1 = o1*ftanh(creg.y);
            *(float2*)(out + ((size_t)t*BB + b)*HH + n2) = make_float2(h0, h1);

            // int8 split: h = (q + p/256)/127
            int q0 = clamp127(__float2int_rn(h0*127.f));
            int q1 = clamp127(__float2int_rn(h1*127.f));
            int p0 = clamp127(__float2int_rn((h0*127.f - (float)q0)*256.f));
            int p1 = clamp127(__float2int_rn((h1*127.f - (float)q1)*256.f));
            char2 c1; c1.x = (char)q0; c1.y = (char)q1;
            char2 c2; c2.x = (char)p0; c2.y = (char)p1;
            *(char2*)(g_h1 + b*HH + n2) = c1;
            *(char2*)(g_h2 + b*HH + n2) = c2;

            if (t == TT-1){
                *(float2*)(out + (size_t)TT*BH + (size_t)b*HH + n2) = make_float2(h0, h1);
                *(float2*)(out + (size_t)TT*BH + BH + (size_t)b*HH + n2) = creg;
            }
        }

        // ---- grid barrier B ----
        __syncthreads();
        if (tid == 0){
            __threadfence();
            atomicAdd(&g_barcnt, 1u);
            unsigned tgt = 128u*(2u*t + 2u);
            while (*(volatile unsigned*)&g_barcnt < tgt) {}
        }
        __syncthreads();
    }
    #undef LOAD_A
}

// ---------------- launch ----------------
#define SMEM_PRE  65536
#define SMEM_LOOP 140288

extern "C" void kernel_launch(void* const* d_in, const int* in_sizes, int n_in,
                              void* d_out, int out_size)
{
    const float* X   = (const float*)d_in[0];
    const float* Wf  = (const float*)d_in[1];
    const float* bfp = (const float*)d_in[2];
    const float* Wi  = (const float*)d_in[3];
    const float* bip = (const float*)d_in[4];
    const float* Wu  = (const float*)d_in[5];
    const float* bup = (const float*)d_in[6];
    const float* Wo  = (const float*)d_in[7];
    const float* bop = (const float*)d_in[8];
    float* out = (float*)d_out;

    cudaFuncSetAttribute(k_pre,  cudaFuncAttributeMaxDynamicSharedMemorySize, SMEM_PRE);
    cudaFuncSetAttribute(k_loop, cudaFuncAttributeMaxDynamicSharedMemorySize, SMEM_LOOP);

    k_init<<<BH/256, 256>>>(bfp, bip, bup, bop);
    k_cvtX<<<32768, 256>>>(X);
    k_cvtW<<<dim3(1024, 4), 256>>>(Wf, Wi, Wu, Wo);
    k_cvtWh<<<NG, 256>>>(Wf, Wi, Wu, Wo);
    k_pre<<<dim3(32, 256), 256, SMEM_PRE>>>();
    k_loop<<<128, 512, SMEM_LOOP>>>(X, out);
}

// round 14
// speedup vs baseline: 1.8382x; 1.8382x over previous
#include <cuda_runtime.h>
#include <cuda_bf16.h>
#include <math.h>
#include <stdint.h>

#define TT 256
#define BB 128
#define HH 1024
#define DD 1024
#define BH (BB*HH)
#define NG 4096       // 4 gates * 1024
#define KSPLIT 4

// ---------------- device global scratch (no allocs allowed) ----------------
static __device__ float g_Z[(size_t)TT*BB*NG];
static __device__ float g_P[(size_t)KSPLIT*BB*NG];
static __device__ float g_zero[HH];
static __device__ float g_bias[NG];
static __device__ __align__(128) unsigned g_barcnt[8*32];   // 8 counters, 128B apart
static __device__ __align__(16) __nv_bfloat16 g_Xhi[(size_t)TT*BB*DD];
static __device__ __align__(16) __nv_bfloat16 g_Xlo[(size_t)TT*BB*DD];
static __device__ __align__(16) __nv_bfloat16 g_Wxhi[(size_t)NG*HH];
static __device__ __align__(16) __nv_bfloat16 g_Wxlo[(size_t)NG*HH];
static __device__ __align__(16) __nv_bfloat16 g_Whhi[(size_t)NG*HH];
static __device__ __align__(16) __nv_bfloat16 g_Whlo[(size_t)NG*HH];
static __device__ __align__(16) __nv_bfloat16 g_hhi[BH];
static __device__ __align__(16) __nv_bfloat16 g_hlo[BH];

// ---------------- PTX helpers (baseline ISA only) ----------------
__device__ __forceinline__ uint32_t smem_u32(const void* p){
    uint32_t a;
    asm("{ .reg .u64 t; cvta.to.shared.u64 t, %1; cvt.u32.u64 %0, t; }" : "=r"(a) : "l"(p));
    return a;
}
__device__ __forceinline__ void ldsm4(uint32_t& r0, uint32_t& r1, uint32_t& r2, uint32_t& r3, uint32_t a){
    asm volatile("ldmatrix.sync.aligned.m8n8.x4.shared.b16 {%0,%1,%2,%3}, [%4];"
                 : "=r"(r0), "=r"(r1), "=r"(r2), "=r"(r3) : "r"(a));
}
__device__ __forceinline__ void mma16816(float* d, const uint32_t* a, const uint32_t* b){
    asm volatile("mma.sync.aligned.m16n8k16.row.col.f32.bf16.bf16.f32 "
                 "{%0,%1,%2,%3}, {%4,%5,%6,%7}, {%8,%9}, {%0,%1,%2,%3};"
                 : "+f"(d[0]), "+f"(d[1]), "+f"(d[2]), "+f"(d[3])
                 : "r"(a[0]), "r"(a[1]), "r"(a[2]), "r"(a[3]), "r"(b[0]), "r"(b[1]));
}
__device__ __forceinline__ void cpa16(uint32_t dst, const void* src){
    asm volatile("cp.async.cg.shared.global [%0], [%1], 16;" :: "r"(dst), "l"(src));
}
#define CP_COMMIT asm volatile("cp.async.commit_group;" ::: "memory")
#define CP_WAIT1  asm volatile("cp.async.wait_group 1;" ::: "memory")
#define CP_WAIT0  asm volatile("cp.async.wait_group 0;" ::: "memory")

__device__ __forceinline__ float fsig(float x){ return 1.f/(1.f + __expf(-x)); }
__device__ __forceinline__ float ftanh(float x){ return 1.f - 2.f/(__expf(2.f*x) + 1.f); }

// distributed grid barrier: 8 counters (16 CTAs each), poll all 8 with plain loads.
__device__ __forceinline__ void bar_dist(int bid, int tid, unsigned ph){
    __syncthreads();
    if (tid == 0){
        __threadfence();
        atomicAdd(&g_barcnt[(bid >> 4)*32], 1u);
    }
    if (tid < 8){
        unsigned tgt = 16u*ph;
        while (*(volatile unsigned*)&g_barcnt[tid*32] < tgt) {}
    }
    __syncthreads();
}

// ---------------- init ----------------
__global__ void k_init(const float* __restrict__ bf, const float* __restrict__ bi,
                       const float* __restrict__ bu, const float* __restrict__ bo){
    int i = blockIdx.x*256 + threadIdx.x;      // grid covers BH
    g_hhi[i] = __float2bfloat16(0.f);
    g_hlo[i] = __float2bfloat16(0.f);
    if (i < HH) g_zero[i] = 0.f;
    if (i < NG){
        int g = i >> 10, n = i & 1023;
        g_bias[i] = (g==0?bf:g==1?bi:g==2?bu:bo)[n];
    }
    if (i < 8*32) g_barcnt[i] = 0u;
}

// ---------------- fp32 -> bf16 hi/lo split ----------------
__device__ __forceinline__ void split4(float4 a, uint2& hi, uint2& lo){
    union { __nv_bfloat16 b[4]; uint2 u; } H, L;
    float x[4] = {a.x, a.y, a.z, a.w};
    #pragma unroll
    for (int j=0;j<4;j++){
        __nv_bfloat16 h = __float2bfloat16(x[j]);
        H.b[j] = h;
        L.b[j] = __float2bfloat16(x[j] - __bfloat162float(h));
    }
    hi = H.u; lo = L.u;
}

__global__ __launch_bounds__(256) void k_cvtX(const float* __restrict__ X){
    size_t v = (size_t)blockIdx.x*256 + threadIdx.x;
    float4 a = *(const float4*)(X + v*4);
    uint2 hi, lo; split4(a, hi, lo);
    *(uint2*)((char*)g_Xhi + v*8) = hi;
    *(uint2*)((char*)g_Xlo + v*8) = lo;
}

__global__ __launch_bounds__(256) void k_cvtW(const float* __restrict__ Wf, const float* __restrict__ Wi,
                                              const float* __restrict__ Wu, const float* __restrict__ Wo){
    int g = blockIdx.y;
    const float* __restrict__ W = (g==0)?Wf:(g==1)?Wi:(g==2)?Wu:Wo;
    int v = blockIdx.x*256 + threadIdx.x;
    int n  = v >> 8;
    int kv = (v & 255) * 4;
    size_t o = ((size_t)g*1024 + n)*1024 + kv;
    float4 ax = *(const float4*)(W + (size_t)n*2048 + kv);
    float4 ah = *(const float4*)(W + (size_t)n*2048 + 1024 + kv);
    uint2 hi, lo;
    split4(ax, hi, lo);
    *(uint2*)((char*)g_Wxhi + o*2) = hi;
    *(uint2*)((char*)g_Wxlo + o*2) = lo;
    split4(ah, hi, lo);
    *(uint2*)((char*)g_Whhi + o*2) = hi;
    *(uint2*)((char*)g_Whlo + o*2) = lo;
}

// ---------------- precompute GEMM (R6-proven: tensor=74%) ----------
__global__ __launch_bounds__(256, 2) void k_pre(){
    extern __shared__ char smem[];
    const uint32_t sbase = smem_u32(smem);
    const int tid  = threadIdx.x;
    const int lane = tid & 31;
    const int wid  = tid >> 5;
    const int wm   = wid >> 1;
    const int wn   = wid & 1;
    const int n0   = blockIdx.x * 128;
    const int y    = blockIdx.y;

    const __nv_bfloat16* Ah = g_Xhi + (size_t)y*131072;
    const __nv_bfloat16* Al = g_Xlo + (size_t)y*131072;
    const __nv_bfloat16* Bh = g_Wxhi + (size_t)n0*1024;
    const __nv_bfloat16* Bl = g_Wxlo + (size_t)n0*1024;
    float* out = g_Z + (size_t)y*BB*NG;

    float acc[2][8][4];
    #pragma unroll
    for (int i=0;i<2;i++)
        #pragma unroll
        for (int j=0;j<8;j++)
            #pragma unroll
            for (int q=0;q<4;q++) acc[i][j][q] = 0.f;

    int lrow[2], ldst[2], lgc[2];
    #pragma unroll
    for (int i=0;i<2;i++){
        int ch = tid + i*256;
        int r = ch >> 2, c = ch & 3;
        lrow[i] = r; lgc[i] = c*8;
        ldst[i] = r*64 + ((c ^ ((r>>1)&3))<<4);
    }

    #define LOAD_SLAB(stg, ks) do {                                   \
        uint32_t sb_ = sbase + (stg)*32768;                            \
        _Pragma("unroll")                                              \
        for (int i_=0;i_<2;i_++){                                      \
            size_t go_ = (size_t)lrow[i_]*1024 + (ks) + lgc[i_];       \
            cpa16(sb_ + ldst[i_],          Ah + go_);                  \
            cpa16(sb_ + 8192  + ldst[i_],  Al + go_);                  \
            cpa16(sb_ + 16384 + ldst[i_],  Bh + go_);                  \
            cpa16(sb_ + 24576 + ldst[i_],  Bl + go_);                  \
        }                                                              \
    } while(0)

    LOAD_SLAB(0, 0);
    CP_COMMIT;

    for (int s = 0; s < 32; s++){
        if (s+1 < 32){ LOAD_SLAB((s+1)&1, (s+1)*32); CP_COMMIT; CP_WAIT1; }
        else CP_WAIT0;
        __syncthreads();

        const uint32_t sA = sbase + (s&1)*32768;
        const uint32_t sB = sA + 16384;
        #pragma unroll
        for (int kk = 0; kk < 2; kk++){
            uint32_t ah[2][4], al[2][4];
            #pragma unroll
            for (int mt=0; mt<2; mt++){
                int r = wm*32 + mt*16 + (lane & 15);
                int c = kk*2 + (lane >> 4);
                uint32_t ad = sA + r*64 + (((c ^ ((r>>1)&3)))<<4);
                ldsm4(ah[mt][0], ah[mt][1], ah[mt][2], ah[mt][3], ad);
                ldsm4(al[mt][0], al[mt][1], al[mt][2], al[mt][3], ad + 8192);
            }
            #pragma unroll
            for (int ntp=0; ntp<4; ntp++){
                int q = lane >> 3;
                int n = wn*64 + ntp*16 + ((q>>1)<<3) + (lane & 7);
                int kc = kk*2 + (q & 1);
                uint32_t bd = sB + n*64 + (((kc ^ ((n>>1)&3)))<<4);
                uint32_t bh[4], bl[4];
                ldsm4(bh[0], bh[1], bh[2], bh[3], bd);
                ldsm4(bl[0], bl[1], bl[2], bl[3], bd + 8192);
                #pragma unroll
                for (int mt=0; mt<2; mt++){
                    mma16816(acc[mt][2*ntp],   ah[mt], bh);
                    mma16816(acc[mt][2*ntp],   ah[mt], bl);
                    mma16816(acc[mt][2*ntp],   al[mt], bh);
                    mma16816(acc[mt][2*ntp+1], ah[mt], bh+2);
                    mma16816(acc[mt][2*ntp+1], ah[mt], bl+2);
                    mma16816(acc[mt][2*ntp+1], al[mt], bh+2);
                }
            }
        }
        __syncthreads();
    }
    #undef LOAD_SLAB

    #pragma unroll
    for (int mt=0; mt<2; mt++){
        int m = wm*32 + mt*16 + (lane >> 2);
        #pragma unroll
        for (int nt=0; nt<8; nt++){
            int nc = n0 + wn*64 + nt*8 + (lane & 3)*2;
            float b0 = g_bias[nc], b1 = g_bias[nc+1];
            float2 v0 = make_float2(acc[mt][nt][0] + b0, acc[mt][nt][1] + b1);
            float2 v1 = make_float2(acc[mt][nt][2] + b0, acc[mt][nt][3] + b1);
            *(float2*)(out + (size_t)m*NG + nc)     = v0;
            *(float2*)(out + (size_t)(m+8)*NG + nc) = v1;
        }
    }
}

// ---------------- persistent recurrent kernel (512 threads, BK=32, 3-stage) ----
// Smem: Wh_hi [8 x 8KB] @0 | Wh_lo @64K | A 3-stage @128K (3 x 16KB) | pf @176K (24KB)
#define ASTAGE_OFF 131072
#define PF_OFF     180224
__global__ __launch_bounds__(512) void k_loop(const float* __restrict__ X,
                                              float* __restrict__ out){
    extern __shared__ char smem[];
    __shared__ float red[16];
    const uint32_t sbase = smem_u32(smem);
    const int tid  = threadIdx.x;
    const int lane = tid & 31;
    const int wid  = tid >> 5;
    const int wm   = wid & 3;      // M group: 4 x 32 rows
    const int wn   = wid >> 2;     // N group: 4 x 32 cols
    const int bid  = blockIdx.x;
    const int nt   = bid & 31;
    const int ks   = bid >> 5;
    const int n0   = nt * 128;
    const int b    = bid;

    // load geometry: 512 threads cover one 8KB plane (128 rows x 4 chunks)
    const int lrow = tid >> 2, lch = tid & 3;
    const uint32_t ldst = lrow*64 + ((lch ^ ((lrow>>1)&3))<<4);
    const int lgc = lch*8;

    // ---- resident weights (once) ----
    {
        const __nv_bfloat16* Wh = g_Whhi + (size_t)n0*1024 + ks*256;
        const __nv_bfloat16* Wl = g_Whlo + (size_t)n0*1024 + ks*256;
        #pragma unroll
        for (int s=0; s<8; s++){
            size_t go = (size_t)lrow*1024 + s*32 + lgc;
            cpa16(sbase + s*8192 + ldst,         Wh + go);
            cpa16(sbase + 65536 + s*8192 + ldst, Wl + go);
        }
        CP_COMMIT; CP_WAIT0;
        __syncthreads();
    }

    const uint32_t sAbase = sbase + ASTAGE_OFF;
    const __nv_bfloat16* Ah = g_hhi + ks*256;
    const __nv_bfloat16* Al = g_hlo + ks*256;
    float* Pout = g_P + (size_t)ks*BB*NG + n0;
    const char* smc = smem;
    const float* xsp  = (const float*)(smc + PF_OFF);
    const float* hpsp = (const float*)(smc + PF_OFF + 4096);
    const float* Zsp  = (const float*)(smc + PF_OFF + 8192);

    float2 creg = make_float2(0.f, 0.f);   // cell state, units 2*tid, 2*tid+1

    #define LOAD_A(stg, s_) do {                                        \
        uint32_t sb_ = sAbase + (stg)*16384;                             \
        size_t go_ = (size_t)lrow*1024 + (s_)*32 + lgc;                  \
        cpa16(sb_ + ldst,        Ah + go_);                              \
        cpa16(sb_ + 8192 + ldst, Al + go_);                              \
    } while(0)

    for (int t = 0; t < TT; t++){
        // ---- prefetch x, h_prev, Z (1536 16B-chunks over 512 threads) ----
        {
            const float* xr = X + ((size_t)t*BB + b)*DD;
            const float* hp = t ? (out + ((size_t)(t-1)*BB + b)*HH) : g_zero;
            const float* Zr = g_Z + ((size_t)t*BB + b)*NG;
            #pragma unroll
            for (int i=0;i<3;i++){
                int cidx = tid + i*512;
                if (cidx < 256)       cpa16(sbase + PF_OFF + cidx*16, xr + cidx*4);
                else if (cidx < 512)  cpa16(sbase + PF_OFF + 4096 + (cidx-256)*16, hp + (cidx-256)*4);
                else                  cpa16(sbase + PF_OFF + 8192 + (cidx-512)*16, Zr + (cidx-512)*4);
            }
        }

        // ======== GEMM phase: 3-stage pipeline, ONE sync per slab ========
        float acc[2][4][4];
        #pragma unroll
        for (int i=0;i<2;i++)
            #pragma unroll
            for (int j=0;j<4;j++)
                #pragma unroll
                for (int q=0;q<4;q++) acc[i][j][q] = 0.f;

        LOAD_A(0, 0); CP_COMMIT;   // g0: prefetch + slab0
        LOAD_A(1, 1); CP_COMMIT;   // g1: slab1
        for (int s = 0; s < 8; s++){
            if (s < 7) CP_WAIT1; else CP_WAIT0;   // slab s resident
            __syncthreads();                       // all warps see stage s%3
            if (s + 2 < 8){ LOAD_A((s+2)%3, s+2); CP_COMMIT; }

            const uint32_t sA  = sAbase + (s%3)*16384;
            const uint32_t sBh = sbase + s*8192;
            #pragma unroll
            for (int kk = 0; kk < 2; kk++){
                uint32_t ah[2][4], al[2][4], bh[2][4], bl[2][4];
                #pragma unroll
                for (int mt=0; mt<2; mt++){
                    int r = wm*32 + mt*16 + (lane & 15);
                    int c = kk*2 + (lane >> 4);
                    uint32_t ad = sA + r*64 + (((c ^ ((r>>1)&3)))<<4);
                    ldsm4(ah[mt][0], ah[mt][1], ah[mt][2], ah[mt][3], ad);
                    ldsm4(al[mt][0], al[mt][1], al[mt][2], al[mt][3], ad + 8192);
                }
                #pragma unroll
                for (int ntp=0; ntp<2; ntp++){
                    int q = lane >> 3;
                    int n = wn*32 + ntp*16 + ((q>>1)<<3) + (lane & 7);
                    int kc = kk*2 + (q & 1);
                    uint32_t bd = sBh + n*64 + (((kc ^ ((n>>1)&3)))<<4);
                    ldsm4(bh[ntp][0], bh[ntp][1], bh[ntp][2], bh[ntp][3], bd);
                    ldsm4(bl[ntp][0], bl[ntp][1], bl[ntp][2], bl[ntp][3], bd + 65536);
                }
                // term-ordered issue: accumulator reuse distance = 8 MMAs
                #pragma unroll
                for (int mt=0; mt<2; mt++)
                    #pragma unroll
                    for (int ntp=0; ntp<2; ntp++){
                        mma16816(acc[mt][2*ntp],   ah[mt], bh[ntp]);
                        mma16816(acc[mt][2*ntp+1], ah[mt], bh[ntp]+2);
                    }
                #pragma unroll
                for (int mt=0; mt<2; mt++)
                    #pragma unroll
                    for (int ntp=0; ntp<2; ntp++){
                        mma16816(acc[mt][2*ntp],   ah[mt], bl[ntp]);
                        mma16816(acc[mt][2*ntp+1], ah[mt], bl[ntp]+2);
                    }
                #pragma unroll
                for (int mt=0; mt<2; mt++)
                    #pragma unroll
                    for (int ntp=0; ntp<2; ntp++){
                        mma16816(acc[mt][2*ntp],   al[mt], bh[ntp]);
                        mma16816(acc[mt][2*ntp+1], al[mt], bh[ntp]+2);
                    }
            }
            // no end-of-iteration sync: 3-stage rotation makes it redundant
        }

        // epilogue: write partials
        #pragma unroll
        for (int mt=0; mt<2; mt++){
            int m = wm*32 + mt*16 + (lane >> 2);
            #pragma unroll
            for (int j=0; j<4; j++){
                int nc = wn*32 + j*8 + (lane & 3)*2;
                *(float2*)(Pout + (size_t)m*NG + nc)
                    = make_float2(acc[mt][j][0], acc[mt][j][1]);
                *(float2*)(Pout + (size_t)(m+8)*NG + nc)
                    = make_float2(acc[mt][j][2], acc[mt][j][3]);
            }
        }

        // ---- RBF partial BEFORE barrier A (uses only prefetched smem) ----
        {
            const int n2 = 2*tid;
            float2 xv = *(const float2*)(xsp + n2);
            float2 hv = *(const float2*)(hpsp + n2);
            float d0 = xv.x - hv.x, d1 = xv.y - hv.y;
            float sacc = d0*d0 + d1*d1;
            #pragma unroll
            for (int o=16;o;o>>=1) sacc += __shfl_xor_sync(0xFFFFFFFFu, sacc, o);
            if (lane == 0) red[wid] = sacc;
        }

        // ---- grid barrier A (distributed counters) ----
        bar_dist(bid, tid, 2u*t + 1u);

        // ======== elementwise phase: batch row b, units 2*tid, 2*tid+1 ========
        {
            const int n2 = 2*tid;
            float tot = 0.f;
            #pragma unroll
            for (int w=0; w<16; w++) tot += red[w];
            const float kk_ = __expf(-tot);

            float2 pf = *(const float2*)(Zsp + n2);
            float2 pi = *(const float2*)(Zsp + 1024 + n2);
            float2 pu = *(const float2*)(Zsp + 2048 + n2);
            float2 po = *(const float2*)(Zsp + 3072 + n2);
            #pragma unroll
            for (int sp=0; sp<KSPLIT; sp++){
                const float* P = g_P + ((size_t)sp*BB + b)*NG;
                float2 a0 = __ldcg((const float2*)(P + n2));
                float2 a1 = __ldcg((const float2*)(P + 1024 + n2));
                float2 a2 = __ldcg((const float2*)(P + 2048 + n2));
                float2 a3 = __ldcg((const float2*)(P + 3072 + n2));
                pf.x += a0.x; pf.y += a0.y;
                pi.x += a1.x; pi.y += a1.y;
                pu.x += a2.x; pu.y += a2.y;
                po.x += a3.x; po.y += a3.y;
            }
            float f0 = fsig(pf.x + kk_), f1 = fsig(pf.y + kk_);
            float i0 = fsig(pi.x + kk_), i1 = fsig(pi.y + kk_);
            float u0 = ftanh(pu.x),      u1 = ftanh(pu.y);
            float o0 = fsig(po.x + kk_), o1 = fsig(po.y + kk_);
            creg.x = f0*creg.x + i0*u0;
            creg.y = f1*creg.y + i1*u1;
            float h0 = o0*ftanh(creg.x);
            float h1 = o1*ftanh(creg.y);
            *(float2*)(out + ((size_t)t*BB + b)*HH + n2) = make_float2(h0, h1);
            __nv_bfloat16 hh0 = __float2bfloat16(h0);
            __nv_bfloat16 hh1 = __float2bfloat16(h1);
            union { __nv_bfloat16 bb[2]; uint32_t u; } HI, LO;
            HI.bb[0] = hh0; HI.bb[1] = hh1;
            LO.bb[0] = __float2bfloat16(h0 - __bfloat162float(hh0));
            LO.bb[1] = __float2bfloat16(h1 - __bfloat162float(hh1));
            *(uint32_t*)(g_hhi + b*HH + n2) = HI.u;
            *(uint32_t*)(g_hlo + b*HH + n2) = LO.u;
            if (t == TT-1){
                *(float2*)(out + (size_t)TT*BH + (size_t)b*HH + n2) = make_float2(h0, h1);
                *(float2*)(out + (size_t)TT*BH + BH + (size_t)b*HH + n2) = creg;
            }
        }

        // ---- grid barrier B (distributed counters) ----
        bar_dist(bid, tid, 2u*t + 2u);
    }
    #undef LOAD_A
}

// ---------------- launch ----------------
#define SMEM_PRE  65536
#define SMEM_LOOP 204800

extern "C" void kernel_launch(void* const* d_in, const int* in_sizes, int n_in,
                              void* d_out, int out_size)
{
    const float* X   = (const float*)d_in[0];
    const float* Wf  = (const float*)d_in[1];
    const float* bfp = (const float*)d_in[2];
    const float* Wi  = (const float*)d_in[3];
    const float* bip = (const float*)d_in[4];
    const float* Wu  = (const float*)d_in[5];
    const float* bup = (const float*)d_in[6];
    const float* Wo  = (const float*)d_in[7];
    const float* bop = (const float*)d_in[8];
    float* out = (float*)d_out;

    cudaFuncSetAttribute(k_pre,  cudaFuncAttributeMaxDynamicSharedMemorySize, SMEM_PRE);
    cudaFuncSetAttribute(k_loop, cudaFuncAttributeMaxDynamicSharedMemorySize, SMEM_LOOP);

    k_init<<<BH/256, 256>>>(bfp, bip, bup, bop);
    k_cvtX<<<32768, 256>>>(X);
    k_cvtW<<<dim3(1024, 4), 256>>>(Wf, Wi, Wu, Wo);
    k_pre<<<dim3(32, 256), 256, SMEM_PRE>>>();
    k_loop<<<128, 512, SMEM_LOOP>>>(X, out);
}

// round 15
// speedup vs baseline: 1.8905x; 1.0284x over previous
#include <cuda_runtime.h>
#include <cuda_bf16.h>
#include <math.h>
#include <stdint.h>

#define TT 256
#define BB 128
#define HH 1024
#define DD 1024
#define BH (BB*HH)
#define NG 4096       // 4 gates * 1024
#define KSPLIT 4

// ---------------- device global scratch (no allocs allowed) ----------------
static __device__ float g_Z[(size_t)TT*BB*NG];
static __device__ float g_P[(size_t)KSPLIT*BB*NG];
static __device__ float g_zero[HH];
static __device__ float g_bias[NG];
static __device__ unsigned g_barcnt;
static __device__ __align__(16) __nv_bfloat16 g_Xhi[(size_t)TT*BB*DD];
static __device__ __align__(16) __nv_bfloat16 g_Xlo[(size_t)TT*BB*DD];
static __device__ __align__(16) __nv_bfloat16 g_Wxhi[(size_t)NG*HH];
static __device__ __align__(16) __nv_bfloat16 g_Wxlo[(size_t)NG*HH];
static __device__ __align__(16) __nv_bfloat16 g_Whhi[(size_t)NG*HH];
static __device__ __align__(16) __nv_bfloat16 g_Whlo[(size_t)NG*HH];
static __device__ __align__(16) __nv_bfloat16 g_hhi[BH];
static __device__ __align__(16) __nv_bfloat16 g_hlo[BH];

// ---------------- PTX helpers (baseline ISA only) ----------------
__device__ __forceinline__ uint32_t smem_u32(const void* p){
    uint32_t a;
    asm("{ .reg .u64 t; cvta.to.shared.u64 t, %1; cvt.u32.u64 %0, t; }" : "=r"(a) : "l"(p));
    return a;
}
__device__ __forceinline__ void ldsm4(uint32_t& r0, uint32_t& r1, uint32_t& r2, uint32_t& r3, uint32_t a){
    asm volatile("ldmatrix.sync.aligned.m8n8.x4.shared.b16 {%0,%1,%2,%3}, [%4];"
                 : "=r"(r0), "=r"(r1), "=r"(r2), "=r"(r3) : "r"(a));
}
__device__ __forceinline__ void mma16816(float* d, const uint32_t* a, const uint32_t* b){
    asm volatile("mma.sync.aligned.m16n8k16.row.col.f32.bf16.bf16.f32 "
                 "{%0,%1,%2,%3}, {%4,%5,%6,%7}, {%8,%9}, {%0,%1,%2,%3};"
                 : "+f"(d[0]), "+f"(d[1]), "+f"(d[2]), "+f"(d[3])
                 : "r"(a[0]), "r"(a[1]), "r"(a[2]), "r"(a[3]), "r"(b[0]), "r"(b[1]));
}
__device__ __forceinline__ void cpa16(uint32_t dst, const void* src){
    asm volatile("cp.async.cg.shared.global [%0], [%1], 16;" :: "r"(dst), "l"(src));
}
#define CP_COMMIT asm volatile("cp.async.commit_group;" ::: "memory")
#define CP_WAIT1  asm volatile("cp.async.wait_group 1;" ::: "memory")
#define CP_WAIT0  asm volatile("cp.async.wait_group 0;" ::: "memory")

__device__ __forceinline__ float fsig(float x){ return 1.f/(1.f + __expf(-x)); }
__device__ __forceinline__ float ftanh(float x){ return 1.f - 2.f/(__expf(2.f*x) + 1.f); }

// ---------------- init ----------------
__global__ void k_init(const float* __restrict__ bf, const float* __restrict__ bi,
                       const float* __restrict__ bu, const float* __restrict__ bo){
    int i = blockIdx.x*256 + threadIdx.x;      // grid covers BH
    g_hhi[i] = __float2bfloat16(0.f);
    g_hlo[i] = __float2bfloat16(0.f);
    if (i < HH) g_zero[i] = 0.f;
    if (i < NG){
        int g = i >> 10, n = i & 1023;
        g_bias[i] = (g==0?bf:g==1?bi:g==2?bu:bo)[n];
    }
    if (i == 0) g_barcnt = 0u;
}

// ---------------- fp32 -> bf16 hi/lo split ----------------
__device__ __forceinline__ void split4(float4 a, uint2& hi, uint2& lo){
    union { __nv_bfloat16 b[4]; uint2 u; } H, L;
    float x[4] = {a.x, a.y, a.z, a.w};
    #pragma unroll
    for (int j=0;j<4;j++){
        __nv_bfloat16 h = __float2bfloat16(x[j]);
        H.b[j] = h;
        L.b[j] = __float2bfloat16(x[j] - __bfloat162float(h));
    }
    hi = H.u; lo = L.u;
}

__global__ __launch_bounds__(256) void k_cvtX(const float* __restrict__ X){
    size_t v = (size_t)blockIdx.x*256 + threadIdx.x;
    float4 a = *(const float4*)(X + v*4);
    uint2 hi, lo; split4(a, hi, lo);
    *(uint2*)((char*)g_Xhi + v*8) = hi;
    *(uint2*)((char*)g_Xlo + v*8) = lo;
}

__global__ __launch_bounds__(256) void k_cvtW(const float* __restrict__ Wf, const float* __restrict__ Wi,
                                              const float* __restrict__ Wu, const float* __restrict__ Wo){
    int g = blockIdx.y;
    const float* __restrict__ W = (g==0)?Wf:(g==1)?Wi:(g==2)?Wu:Wo;
    int v = blockIdx.x*256 + threadIdx.x;
    int n  = v >> 8;
    int kv = (v & 255) * 4;
    size_t o = ((size_t)g*1024 + n)*1024 + kv;
    float4 ax = *(const float4*)(W + (size_t)n*2048 + kv);
    float4 ah = *(const float4*)(W + (size_t)n*2048 + 1024 + kv);
    uint2 hi, lo;
    split4(ax, hi, lo);
    *(uint2*)((char*)g_Wxhi + o*2) = hi;
    *(uint2*)((char*)g_Wxlo + o*2) = lo;
    split4(ah, hi, lo);
    *(uint2*)((char*)g_Whhi + o*2) = hi;
    *(uint2*)((char*)g_Whlo + o*2) = lo;
}

// ---------------- precompute GEMM (R6-proven: tensor=74%) ----------
__global__ __launch_bounds__(256, 2) void k_pre(){
    extern __shared__ char smem[];
    const uint32_t sbase = smem_u32(smem);
    const int tid  = threadIdx.x;
    const int lane = tid & 31;
    const int wid  = tid >> 5;
    const int wm   = wid >> 1;
    const int wn   = wid & 1;
    const int n0   = blockIdx.x * 128;
    const int y    = blockIdx.y;

    const __nv_bfloat16* Ah = g_Xhi + (size_t)y*131072;
    const __nv_bfloat16* Al = g_Xlo + (size_t)y*131072;
    const __nv_bfloat16* Bh = g_Wxhi + (size_t)n0*1024;
    const __nv_bfloat16* Bl = g_Wxlo + (size_t)n0*1024;
    float* out = g_Z + (size_t)y*BB*NG;

    float acc[2][8][4];
    #pragma unroll
    for (int i=0;i<2;i++)
        #pragma unroll
        for (int j=0;j<8;j++)
            #pragma unroll
            for (int q=0;q<4;q++) acc[i][j][q] = 0.f;

    int lrow[2], ldst[2], lgc[2];
    #pragma unroll
    for (int i=0;i<2;i++){
        int ch = tid + i*256;
        int r = ch >> 2, c = ch & 3;
        lrow[i] = r; lgc[i] = c*8;
        ldst[i] = r*64 + ((c ^ ((r>>1)&3))<<4);
    }

    #define LOAD_SLAB(stg, ks) do {                                   \
        uint32_t sb_ = sbase + (stg)*32768;                            \
        _Pragma("unroll")                                              \
        for (int i_=0;i_<2;i_++){                                      \
            size_t go_ = (size_t)lrow[i_]*1024 + (ks) + lgc[i_];       \
            cpa16(sb_ + ldst[i_],          Ah + go_);                  \
            cpa16(sb_ + 8192  + ldst[i_],  Al + go_);                  \
            cpa16(sb_ + 16384 + ldst[i_],  Bh + go_);                  \
            cpa16(sb_ + 24576 + ldst[i_],  Bl + go_);                  \
        }                                                              \
    } while(0)

    LOAD_SLAB(0, 0);
    CP_COMMIT;

    for (int s = 0; s < 32; s++){
        if (s+1 < 32){ LOAD_SLAB((s+1)&1, (s+1)*32); CP_COMMIT; CP_WAIT1; }
        else CP_WAIT0;
        __syncthreads();

        const uint32_t sA = sbase + (s&1)*32768;
        const uint32_t sB = sA + 16384;
        #pragma unroll
        for (int kk = 0; kk < 2; kk++){
            uint32_t ah[2][4], al[2][4];
            #pragma unroll
            for (int mt=0; mt<2; mt++){
                int r = wm*32 + mt*16 + (lane & 15);
                int c = kk*2 + (lane >> 4);
                uint32_t ad = sA + r*64 + (((c ^ ((r>>1)&3)))<<4);
                ldsm4(ah[mt][0], ah[mt][1], ah[mt][2], ah[mt][3], ad);
                ldsm4(al[mt][0], al[mt][1], al[mt][2], al[mt][3], ad + 8192);
            }
            #pragma unroll
            for (int ntp=0; ntp<4; ntp++){
                int q = lane >> 3;
                int n = wn*64 + ntp*16 + ((q>>1)<<3) + (lane & 7);
                int kc = kk*2 + (q & 1);
                uint32_t bd = sB + n*64 + (((kc ^ ((n>>1)&3)))<<4);
                uint32_t bh[4], bl[4];
                ldsm4(bh[0], bh[1], bh[2], bh[3], bd);
                ldsm4(bl[0], bl[1], bl[2], bl[3], bd + 8192);
                #pragma unroll
                for (int mt=0; mt<2; mt++){
                    mma16816(acc[mt][2*ntp],   ah[mt], bh);
                    mma16816(acc[mt][2*ntp],   ah[mt], bl);
                    mma16816(acc[mt][2*ntp],   al[mt], bh);
                    mma16816(acc[mt][2*ntp+1], ah[mt], bh+2);
                    mma16816(acc[mt][2*ntp+1], ah[mt], bl+2);
                    mma16816(acc[mt][2*ntp+1], al[mt], bh+2);
                }
            }
        }
        __syncthreads();
    }
    #undef LOAD_SLAB

    #pragma unroll
    for (int mt=0; mt<2; mt++){
        int m = wm*32 + mt*16 + (lane >> 2);
        #pragma unroll
        for (int nt=0; nt<8; nt++){
            int nc = n0 + wn*64 + nt*8 + (lane & 3)*2;
            float b0 = g_bias[nc], b1 = g_bias[nc+1];
            float2 v0 = make_float2(acc[mt][nt][0] + b0, acc[mt][nt][1] + b1);
            float2 v1 = make_float2(acc[mt][nt][2] + b0, acc[mt][nt][3] + b1);
            *(float2*)(out + (size_t)m*NG + nc)     = v0;
            *(float2*)(out + (size_t)(m+8)*NG + nc) = v1;
        }
    }
}

// ---------------- persistent recurrent kernel (512 threads, BK=32, 3-stage) ----
// Smem: Wh_hi [8 x 8KB] @0 | Wh_lo @64K | A 3-stage @128K (3 x 16KB) | pf @176K (24KB)
// pf layout: x @+0 (4KB) | hp @+4096 (4KB) | Z @+8192 (16KB)
// x/Z for step t+1 are prefetched DURING barrier B of step t (h-independent);
// hp is prefetched at loop top (needs h(t-1), visible after barrier B).
#define ASTAGE_OFF 131072
#define PF_OFF     180224
__global__ __launch_bounds__(512) void k_loop(const float* __restrict__ X,
                                              float* __restrict__ out){
    extern __shared__ char smem[];
    __shared__ float red[16];
    const uint32_t sbase = smem_u32(smem);
    const int tid  = threadIdx.x;
    const int lane = tid & 31;
    const int wid  = tid >> 5;
    const int wm   = wid & 3;      // M group: 4 x 32 rows
    const int wn   = wid >> 2;     // N group: 4 x 32 cols
    const int bid  = blockIdx.x;
    const int nt   = bid & 31;
    const int ks   = bid >> 5;
    const int n0   = nt * 128;
    const int b    = bid;

    // load geometry: 512 threads cover one 8KB plane (128 rows x 4 chunks)
    const int lrow = tid >> 2, lch = tid & 3;
    const uint32_t ldst = lrow*64 + ((lch ^ ((lrow>>1)&3))<<4);
    const int lgc = lch*8;

    // ---- resident weights (once) ----
    {
        const __nv_bfloat16* Wh = g_Whhi + (size_t)n0*1024 + ks*256;
        const __nv_bfloat16* Wl = g_Whlo + (size_t)n0*1024 + ks*256;
        #pragma unroll
        for (int s=0; s<8; s++){
            size_t go = (size_t)lrow*1024 + s*32 + lgc;
            cpa16(sbase + s*8192 + ldst,         Wh + go);
            cpa16(sbase + 65536 + s*8192 + ldst, Wl + go);
        }
        CP_COMMIT; CP_WAIT0;
        __syncthreads();
    }

    const uint32_t sAbase = sbase + ASTAGE_OFF;
    const __nv_bfloat16* Ah = g_hhi + ks*256;
    const __nv_bfloat16* Al = g_hlo + ks*256;
    float* Pout = g_P + (size_t)ks*BB*NG + n0;
    const char* smc = smem;
    const float* xsp  = (const float*)(smc + PF_OFF);
    const float* hpsp = (const float*)(smc + PF_OFF + 4096);
    const float* Zsp  = (const float*)(smc + PF_OFF + 8192);

    float2 creg = make_float2(0.f, 0.f);   // cell state, units 2*tid, 2*tid+1

    #define LOAD_A(stg, s_) do {                                        \
        uint32_t sb_ = sAbase + (stg)*16384;                             \
        size_t go_ = (size_t)lrow*1024 + (s_)*32 + lgc;                  \
        cpa16(sb_ + ldst,        Ah + go_);                              \
        cpa16(sb_ + 8192 + ldst, Al + go_);                              \
    } while(0)

    // x/Z prefetch for a step (1280 16B-chunks over 512 threads)
    #define PF_XZ(t_) do {                                               \
        const float* xr_ = X + ((size_t)(t_)*BB + b)*DD;                  \
        const float* Zr_ = g_Z + ((size_t)(t_)*BB + b)*NG;                \
        _Pragma("unroll")                                                 \
        for (int i_=0;i_<3;i_++){                                         \
            int c_ = tid + i_*512;                                        \
            if (c_ < 256)       cpa16(sbase + PF_OFF + c_*16, xr_ + c_*4);\
            else if (c_ < 1280) cpa16(sbase + PF_OFF + 8192 + (c_-256)*16,\
                                      Zr_ + (c_-256)*4);                  \
        }                                                                 \
    } while(0)

    // pre-loop: x/Z for t=0
    PF_XZ(0);
    CP_COMMIT;

    for (int t = 0; t < TT; t++){
        // ---- hp prefetch (h(t-1) visible after barrier B of step t-1) ----
        {
            const float* hp = t ? (out + ((size_t)(t-1)*BB + b)*HH) : g_zero;
            if (tid < 256) cpa16(sbase + PF_OFF + 4096 + tid*16, hp + tid*4);
        }

        // ======== GEMM phase: 3-stage pipeline, ONE sync per slab ========
        float acc[2][4][4];
        #pragma unroll
        for (int i=0;i<2;i++)
            #pragma unroll
            for (int j=0;j<4;j++)
                #pragma unroll
                for (int q=0;q<4;q++) acc[i][j][q] = 0.f;

        LOAD_A(0, 0); CP_COMMIT;   // group: hp + slab0 (x/Z already in-flight)
        LOAD_A(1, 1); CP_COMMIT;   // group: slab1
        for (int s = 0; s < 8; s++){
            if (s < 7) CP_WAIT1; else CP_WAIT0;   // slab s resident
            __syncthreads();                       // all warps see stage s%3
            if (s + 2 < 8){ LOAD_A((s+2)%3, s+2); CP_COMMIT; }

            const uint32_t sA  = sAbase + (s%3)*16384;
            const uint32_t sBh = sbase + s*8192;
            #pragma unroll
            for (int kk = 0; kk < 2; kk++){
                uint32_t ah[2][4], al[2][4], bh[2][4], bl[2][4];
                #pragma unroll
                for (int mt=0; mt<2; mt++){
                    int r = wm*32 + mt*16 + (lane & 15);
                    int c = kk*2 + (lane >> 4);
                    uint32_t ad = sA + r*64 + (((c ^ ((r>>1)&3)))<<4);
                    ldsm4(ah[mt][0], ah[mt][1], ah[mt][2], ah[mt][3], ad);
                    ldsm4(al[mt][0], al[mt][1], al[mt][2], al[mt][3], ad + 8192);
                }
                #pragma unroll
                for (int ntp=0; ntp<2; ntp++){
                    int q = lane >> 3;
                    int n = wn*32 + ntp*16 + ((q>>1)<<3) + (lane & 7);
                    int kc = kk*2 + (q & 1);
                    uint32_t bd = sBh + n*64 + (((kc ^ ((n>>1)&3)))<<4);
                    ldsm4(bh[ntp][0], bh[ntp][1], bh[ntp][2], bh[ntp][3], bd);
                    ldsm4(bl[ntp][0], bl[ntp][1], bl[ntp][2], bl[ntp][3], bd + 65536);
                }
                // term-ordered issue: accumulator reuse distance = 8 MMAs
                #pragma unroll
                for (int mt=0; mt<2; mt++)
                    #pragma unroll
                    for (int ntp=0; ntp<2; ntp++){
                        mma16816(acc[mt][2*ntp],   ah[mt], bh[ntp]);
                        mma16816(acc[mt][2*ntp+1], ah[mt], bh[ntp]+2);
                    }
                #pragma unroll
                for (int mt=0; mt<2; mt++)
                    #pragma unroll
                    for (int ntp=0; ntp<2; ntp++){
                        mma16816(acc[mt][2*ntp],   ah[mt], bl[ntp]);
                        mma16816(acc[mt][2*ntp+1], ah[mt], bl[ntp]+2);
                    }
                #pragma unroll
                for (int mt=0; mt<2; mt++)
                    #pragma unroll
                    for (int ntp=0; ntp<2; ntp++){
                        mma16816(acc[mt][2*ntp],   al[mt], bh[ntp]);
                        mma16816(acc[mt][2*ntp+1], al[mt], bh[ntp]+2);
                    }
            }
            // no end-of-iteration sync: 3-stage rotation makes it redundant
        }

        // epilogue: write partials (L2-direct)
        #pragma unroll
        for (int mt=0; mt<2; mt++){
            int m = wm*32 + mt*16 + (lane >> 2);
            #pragma unroll
            for (int j=0; j<4; j++){
                int nc = wn*32 + j*8 + (lane & 3)*2;
                __stcg((float2*)(Pout + (size_t)m*NG + nc),
                       make_float2(acc[mt][j][0], acc[mt][j][1]));
                __stcg((float2*)(Pout + (size_t)(m+8)*NG + nc),
                       make_float2(acc[mt][j][2], acc[mt][j][3]));
            }
        }

        // ---- RBF partial BEFORE barrier A (uses only prefetched smem) ----
        {
            const int n2 = 2*tid;
            float2 xv = *(const float2*)(xsp + n2);
            float2 hv = *(const float2*)(hpsp + n2);
            float d0 = xv.x - hv.x, d1 = xv.y - hv.y;
            float sacc = d0*d0 + d1*d1;
            #pragma unroll
            for (int o=16;o;o>>=1) sacc += __shfl_xor_sync(0xFFFFFFFFu, sacc, o);
            if (lane == 0) red[wid] = sacc;
        }

        // ---- grid barrier A (single counter; also publishes red[]) ----
        __syncthreads();
        if (tid == 0){
            __threadfence();
            atomicAdd(&g_barcnt, 1u);
            unsigned tgt = 128u*(2u*t + 1u);
            while (*(volatile unsigned*)&g_barcnt < tgt) {}
        }
        __syncthreads();

        // ======== elementwise phase: batch row b, units 2*tid, 2*tid+1 ========
        {
            const int n2 = 2*tid;
            float tot = 0.f;
            #pragma unroll
            for (int w=0; w<16; w++) tot += red[w];
            const float kk_ = __expf(-tot);

            float2 pf = *(const float2*)(Zsp + n2);
            float2 pi = *(const float2*)(Zsp + 1024 + n2);
            float2 pu = *(const float2*)(Zsp + 2048 + n2);
            float2 po = *(const float2*)(Zsp + 3072 + n2);
            #pragma unroll
            for (int sp=0; sp<KSPLIT; sp++){
                const float* P = g_P + ((size_t)sp*BB + b)*NG;
                float2 a0 = __ldcg((const float2*)(P + n2));
                float2 a1 = __ldcg((const float2*)(P + 1024 + n2));
                float2 a2 = __ldcg((const float2*)(P + 2048 + n2));
                float2 a3 = __ldcg((const float2*)(P + 3072 + n2));
                pf.x += a0.x; pf.y += a0.y;
                pi.x += a1.x; pi.y += a1.y;
                pu.x += a2.x; pu.y += a2.y;
                po.x += a3.x; po.y += a3.y;
            }
            float f0 = fsig(pf.x + kk_), f1 = fsig(pf.y + kk_);
            float i0 = fsig(pi.x + kk_), i1 = fsig(pi.y + kk_);
            float u0 = ftanh(pu.x),      u1 = ftanh(pu.y);
            float o0 = fsig(po.x + kk_), o1 = fsig(po.y + kk_);
            creg.x = f0*creg.x + i0*u0;
            creg.y = f1*creg.y + i1*u1;
            float h0 = o0*ftanh(creg.x);
            float h1 = o1*ftanh(creg.y);
            *(float2*)(out + ((size_t)t*BB + b)*HH + n2) = make_float2(h0, h1);
            __nv_bfloat16 hh0 = __float2bfloat16(h0);
            __nv_bfloat16 hh1 = __float2bfloat16(h1);
            union { __nv_bfloat16 bb[2]; uint32_t u; } HI, LO;
            HI.bb[0] = hh0; HI.bb[1] = hh1;
            LO.bb[0] = __float2bfloat16(h0 - __bfloat162float(hh0));
            LO.bb[1] = __float2bfloat16(h1 - __bfloat162float(hh1));
            *(uint32_t*)(g_hhi + b*HH + n2) = HI.u;
            *(uint32_t*)(g_hlo + b*HH + n2) = LO.u;
            if (t == TT-1){
                *(float2*)(out + (size_t)TT*BH + (size_t)b*HH + n2) = make_float2(h0, h1);
                *(float2*)(out + (size_t)TT*BH + BH + (size_t)b*HH + n2) = creg;
            }
        }

        // ---- grid barrier B: arrival, then x/Z prefetch for t+1 issued
        //      INSIDE the spin window (reads of xsp/Zsp completed pre-sync) ----
        __syncthreads();
        if (tid == 0){
            __threadfence();
            atomicAdd(&g_barcnt, 1u);
        }
        if (t + 1 < TT){
            PF_XZ(t + 1);
            CP_COMMIT;
        }
        if (tid == 0){
            unsigned tgt = 128u*(2u*t + 2u);
            while (*(volatile unsigned*)&g_barcnt < tgt) {}
        }
        __syncthreads();
    }
    #undef LOAD_A
    #undef PF_XZ
}

// ---------------- launch ----------------
#define SMEM_PRE  65536
#define SMEM_LOOP 204800

extern "C" void kernel_launch(void* const* d_in, const int* in_sizes, int n_in,
                              void* d_out, int out_size)
{
    const float* X   = (const float*)d_in[0];
    const float* Wf  = (const float*)d_in[1];
    const float* bfp = (const float*)d_in[2];
    const float* Wi  = (const float*)d_in[3];
    const float* bip = (const float*)d_in[4];
    const float* Wu  = (const float*)d_in[5];
    const float* bup = (const float*)d_in[6];
    const float* Wo  = (const float*)d_in[7];
    const float* bop = (const float*)d_in[8];
    float* out = (float*)d_out;

    cudaFuncSetAttribute(k_pre,  cudaFuncAttributeMaxDynamicSharedMemorySize, SMEM_PRE);
    cudaFuncSetAttribute(k_loop, cudaFuncAttributeMaxDynamicSharedMemorySize, SMEM_LOOP);

    k_init<<<BH/256, 256>>>(bfp, bip, bup, bop);
    k_cvtX<<<32768, 256>>>(X);
    k_cvtW<<<dim3(1024, 4), 256>>>(Wf, Wi, Wu, Wo);
    k_pre<<<dim3(32, 256), 256, SMEM_PRE>>>();
    k_loop<<<128, 512, SMEM_LOOP>>>(X, out);
}

// round 16
// speedup vs baseline: 1.9063x; 1.0084x over previous
#include <cuda_runtime.h>
#include <cuda_bf16.h>
#include <math.h>
#include <stdint.h>

#define TT 256
#define BB 128
#define HH 1024
#define DD 1024
#define BH (BB*HH)
#define NG 4096       // 4 gates * 1024
#define KSPLIT 4

// ---------------- device global scratch (no allocs allowed) ----------------
static __device__ float g_Z[(size_t)TT*BB*NG];
static __device__ float g_P[(size_t)KSPLIT*BB*NG];
static __device__ float g_zero[HH];
static __device__ float g_bias[NG];
static __device__ unsigned g_barcnt;
static __device__ __align__(16) __nv_bfloat16 g_Xhi[(size_t)TT*BB*DD];
static __device__ __align__(16) __nv_bfloat16 g_Xlo[(size_t)TT*BB*DD];
static __device__ __align__(16) __nv_bfloat16 g_Wxhi[(size_t)NG*HH];
static __device__ __align__(16) __nv_bfloat16 g_Wxlo[(size_t)NG*HH];
static __device__ __align__(16) __nv_bfloat16 g_Whhi[(size_t)NG*HH];
static __device__ __align__(16) __nv_bfloat16 g_Whlo[(size_t)NG*HH];
static __device__ __align__(16) __nv_bfloat16 g_hhi[BH];
static __device__ __align__(16) __nv_bfloat16 g_hlo[BH];

// ---------------- PTX helpers (baseline ISA only) ----------------
__device__ __forceinline__ uint32_t smem_u32(const void* p){
    uint32_t a;
    asm("{ .reg .u64 t; cvta.to.shared.u64 t, %1; cvt.u32.u64 %0, t; }" : "=r"(a) : "l"(p));
    return a;
}
__device__ __forceinline__ void ldsm4(uint32_t& r0, uint32_t& r1, uint32_t& r2, uint32_t& r3, uint32_t a){
    asm volatile("ldmatrix.sync.aligned.m8n8.x4.shared.b16 {%0,%1,%2,%3}, [%4];"
                 : "=r"(r0), "=r"(r1), "=r"(r2), "=r"(r3) : "r"(a));
}
__device__ __forceinline__ void mma16816(float* d, const uint32_t* a, const uint32_t* b){
    asm volatile("mma.sync.aligned.m16n8k16.row.col.f32.bf16.bf16.f32 "
                 "{%0,%1,%2,%3}, {%4,%5,%6,%7}, {%8,%9}, {%0,%1,%2,%3};"
                 : "+f"(d[0]), "+f"(d[1]), "+f"(d[2]), "+f"(d[3])
                 : "r"(a[0]), "r"(a[1]), "r"(a[2]), "r"(a[3]), "r"(b[0]), "r"(b[1]));
}
__device__ __forceinline__ void cpa16(uint32_t dst, const void* src){
    asm volatile("cp.async.cg.shared.global [%0], [%1], 16;" :: "r"(dst), "l"(src));
}
#define CP_COMMIT asm volatile("cp.async.commit_group;" ::: "memory")
#define CP_WAIT1  asm volatile("cp.async.wait_group 1;" ::: "memory")
#define CP_WAIT0  asm volatile("cp.async.wait_group 0;" ::: "memory")

__device__ __forceinline__ float fsig(float x){ return 1.f/(1.f + __expf(-x)); }
__device__ __forceinline__ float ftanh(float x){ return 1.f - 2.f/(__expf(2.f*x) + 1.f); }

// ---------------- init ----------------
__global__ void k_init(const float* __restrict__ bf, const float* __restrict__ bi,
                       const float* __restrict__ bu, const float* __restrict__ bo){
    int i = blockIdx.x*256 + threadIdx.x;      // grid covers BH
    g_hhi[i] = __float2bfloat16(0.f);
    g_hlo[i] = __float2bfloat16(0.f);
    if (i < HH) g_zero[i] = 0.f;
    if (i < NG){
        int g = i >> 10, n = i & 1023;
        g_bias[i] = (g==0?bf:g==1?bi:g==2?bu:bo)[n];
    }
    if (i == 0) g_barcnt = 0u;
}

// ---------------- fp32 -> bf16 hi/lo split ----------------
__device__ __forceinline__ void split4(float4 a, uint2& hi, uint2& lo){
    union { __nv_bfloat16 b[4]; uint2 u; } H, L;
    float x[4] = {a.x, a.y, a.z, a.w};
    #pragma unroll
    for (int j=0;j<4;j++){
        __nv_bfloat16 h = __float2bfloat16(x[j]);
        H.b[j] = h;
        L.b[j] = __float2bfloat16(x[j] - __bfloat162float(h));
    }
    hi = H.u; lo = L.u;
}

__global__ __launch_bounds__(256) void k_cvtX(const float* __restrict__ X){
    size_t v = (size_t)blockIdx.x*256 + threadIdx.x;
    float4 a = *(const float4*)(X + v*4);
    uint2 hi, lo; split4(a, hi, lo);
    *(uint2*)((char*)g_Xhi + v*8) = hi;
    *(uint2*)((char*)g_Xlo + v*8) = lo;
}

__global__ __launch_bounds__(256) void k_cvtW(const float* __restrict__ Wf, const float* __restrict__ Wi,
                                              const float* __restrict__ Wu, const float* __restrict__ Wo){
    int g = blockIdx.y;
    const float* __restrict__ W = (g==0)?Wf:(g==1)?Wi:(g==2)?Wu:Wo;
    int v = blockIdx.x*256 + threadIdx.x;
    int n  = v >> 8;
    int kv = (v & 255) * 4;
    size_t o = ((size_t)g*1024 + n)*1024 + kv;
    float4 ax = *(const float4*)(W + (size_t)n*2048 + kv);
    float4 ah = *(const float4*)(W + (size_t)n*2048 + 1024 + kv);
    uint2 hi, lo;
    split4(ax, hi, lo);
    *(uint2*)((char*)g_Wxhi + o*2) = hi;
    *(uint2*)((char*)g_Wxlo + o*2) = lo;
    split4(ah, hi, lo);
    *(uint2*)((char*)g_Whhi + o*2) = hi;
    *(uint2*)((char*)g_Whlo + o*2) = lo;
}

// ---------------- precompute GEMM: 3-stage, ONE sync per slab ----------
// Stage = 32KB (Ah 8K | Al 8K | Bh 8K | Bl 8K); 3 stages = 96KB; 2 CTAs/SM.
__global__ __launch_bounds__(256, 2) void k_pre(){
    extern __shared__ char smem[];
    const uint32_t sbase = smem_u32(smem);
    const int tid  = threadIdx.x;
    const int lane = tid & 31;
    const int wid  = tid >> 5;
    const int wm   = wid >> 1;
    const int wn   = wid & 1;
    const int n0   = blockIdx.x * 128;
    const int y    = blockIdx.y;

    const __nv_bfloat16* Ah = g_Xhi + (size_t)y*131072;
    const __nv_bfloat16* Al = g_Xlo + (size_t)y*131072;
    const __nv_bfloat16* Bh = g_Wxhi + (size_t)n0*1024;
    const __nv_bfloat16* Bl = g_Wxlo + (size_t)n0*1024;
    float* out = g_Z + (size_t)y*BB*NG;

    float acc[2][8][4];
    #pragma unroll
    for (int i=0;i<2;i++)
        #pragma unroll
        for (int j=0;j<8;j++)
            #pragma unroll
            for (int q=0;q<4;q++) acc[i][j][q] = 0.f;

    int lrow[2], ldst[2], lgc[2];
    #pragma unroll
    for (int i=0;i<2;i++){
        int ch = tid + i*256;
        int r = ch >> 2, c = ch & 3;
        lrow[i] = r; lgc[i] = c*8;
        ldst[i] = r*64 + ((c ^ ((r>>1)&3))<<4);
    }

    #define LOAD_SLAB(stg, ks) do {                                   \
        uint32_t sb_ = sbase + (stg)*32768;                            \
        _Pragma("unroll")                                              \
        for (int i_=0;i_<2;i_++){                                      \
            size_t go_ = (size_t)lrow[i_]*1024 + (ks) + lgc[i_];       \
            cpa16(sb_ + ldst[i_],          Ah + go_);                  \
            cpa16(sb_ + 8192  + ldst[i_],  Al + go_);                  \
            cpa16(sb_ + 16384 + ldst[i_],  Bh + go_);                  \
            cpa16(sb_ + 24576 + ldst[i_],  Bl + go_);                  \
        }                                                              \
    } while(0)

    LOAD_SLAB(0, 0);  CP_COMMIT;
    LOAD_SLAB(1, 32); CP_COMMIT;

    for (int s = 0; s < 32; s++){
        if (s < 31) CP_WAIT1; else CP_WAIT0;   // slab s resident
        __syncthreads();                        // all warps see stage s%3
        if (s + 2 < 32){ LOAD_SLAB((s+2)%3, (s+2)*32); CP_COMMIT; }

        const uint32_t sA = sbase + (s%3)*32768;
        const uint32_t sB = sA + 16384;
        #pragma unroll
        for (int kk = 0; kk < 2; kk++){
            uint32_t ah[2][4], al[2][4];
            #pragma unroll
            for (int mt=0; mt<2; mt++){
                int r = wm*32 + mt*16 + (lane & 15);
                int c = kk*2 + (lane >> 4);
                uint32_t ad = sA + r*64 + (((c ^ ((r>>1)&3)))<<4);
                ldsm4(ah[mt][0], ah[mt][1], ah[mt][2], ah[mt][3], ad);
                ldsm4(al[mt][0], al[mt][1], al[mt][2], al[mt][3], ad + 8192);
            }
            #pragma unroll
            for (int ntp=0; ntp<4; ntp++){
                int q = lane >> 3;
                int n = wn*64 + ntp*16 + ((q>>1)<<3) + (lane & 7);
                int kc = kk*2 + (q & 1);
                uint32_t bd = sB + n*64 + (((kc ^ ((n>>1)&3)))<<4);
                uint32_t bh[4], bl[4];
                ldsm4(bh[0], bh[1], bh[2], bh[3], bd);
                ldsm4(bl[0], bl[1], bl[2], bl[3], bd + 8192);
                #pragma unroll
                for (int mt=0; mt<2; mt++){
                    mma16816(acc[mt][2*ntp],   ah[mt], bh);
                    mma16816(acc[mt][2*ntp],   ah[mt], bl);
                    mma16816(acc[mt][2*ntp],   al[mt], bh);
                    mma16816(acc[mt][2*ntp+1], ah[mt], bh+2);
                    mma16816(acc[mt][2*ntp+1], ah[mt], bl+2);
                    mma16816(acc[mt][2*ntp+1], al[mt], bh+2);
                }
            }
        }
        // no end-of-iteration sync: 3-stage rotation makes it redundant
    }
    #undef LOAD_SLAB

    #pragma unroll
    for (int mt=0; mt<2; mt++){
        int m = wm*32 + mt*16 + (lane >> 2);
        #pragma unroll
        for (int nt=0; nt<8; nt++){
            int nc = n0 + wn*64 + nt*8 + (lane & 3)*2;
            float b0 = g_bias[nc], b1 = g_bias[nc+1];
            float2 v0 = make_float2(acc[mt][nt][0] + b0, acc[mt][nt][1] + b1);
            float2 v1 = make_float2(acc[mt][nt][2] + b0, acc[mt][nt][3] + b1);
            *(float2*)(out + (size_t)m*NG + nc)     = v0;
            *(float2*)(out + (size_t)(m+8)*NG + nc) = v1;
        }
    }
}

// ---------------- persistent recurrent kernel (512 threads, BK=32, 3-stage) ----
// Smem: Wh_hi [8 x 8KB] @0 | Wh_lo @64K | A 3-stage @128K (3 x 16KB) | pf @176K (24KB)
// pf layout: x @+0 (4KB) | hp @+4096 (4KB, written by EW via STS) | Z @+8192 (16KB)
#define ASTAGE_OFF 131072
#define PF_OFF     180224
__global__ __launch_bounds__(512) void k_loop(const float* __restrict__ X,
                                              float* __restrict__ out){
    extern __shared__ char smem[];
    __shared__ float red[16];
    const uint32_t sbase = smem_u32(smem);
    const int tid  = threadIdx.x;
    const int lane = tid & 31;
    const int wid  = tid >> 5;
    const int wm   = wid & 3;      // M group: 4 x 32 rows
    const int wn   = wid >> 2;     // N group: 4 x 32 cols
    const int bid  = blockIdx.x;
    const int nt   = bid & 31;
    const int ks   = bid >> 5;
    const int n0   = nt * 128;
    const int b    = bid;

    // load geometry: 512 threads cover one 8KB plane (128 rows x 4 chunks)
    const int lrow = tid >> 2, lch = tid & 3;
    const uint32_t ldst = lrow*64 + ((lch ^ ((lrow>>1)&3))<<4);
    const int lgc = lch*8;

    // ---- resident weights (once); hp buffer zeroed for t=0 ----
    {
        const __nv_bfloat16* Wh = g_Whhi + (size_t)n0*1024 + ks*256;
        const __nv_bfloat16* Wl = g_Whlo + (size_t)n0*1024 + ks*256;
        #pragma unroll
        for (int s=0; s<8; s++){
            size_t go = (size_t)lrow*1024 + s*32 + lgc;
            cpa16(sbase + s*8192 + ldst,         Wh + go);
            cpa16(sbase + 65536 + s*8192 + ldst, Wl + go);
        }
        *(float2*)(smem + PF_OFF + 4096 + tid*8) = make_float2(0.f, 0.f);
        CP_COMMIT; CP_WAIT0;
        __syncthreads();
    }

    const uint32_t sAbase = sbase + ASTAGE_OFF;
    const __nv_bfloat16* Ah = g_hhi + ks*256;
    const __nv_bfloat16* Al = g_hlo + ks*256;
    float* Pout = g_P + (size_t)ks*BB*NG + n0;
    const char* smc = smem;
    const float* xsp  = (const float*)(smc + PF_OFF);
    const float* hpsp = (const float*)(smc + PF_OFF + 4096);
    const float* Zsp  = (const float*)(smc + PF_OFF + 8192);

    float2 creg = make_float2(0.f, 0.f);   // cell state, units 2*tid, 2*tid+1

    #define LOAD_A(stg, s_) do {                                        \
        uint32_t sb_ = sAbase + (stg)*16384;                             \
        size_t go_ = (size_t)lrow*1024 + (s_)*32 + lgc;                  \
        cpa16(sb_ + ldst,        Ah + go_);                              \
        cpa16(sb_ + 8192 + ldst, Al + go_);                              \
    } while(0)

    // x/Z prefetch for a step (1280 16B-chunks over 512 threads)
    #define PF_XZ(t_) do {                                               \
        const float* xr_ = X + ((size_t)(t_)*BB + b)*DD;                  \
        const float* Zr_ = g_Z + ((size_t)(t_)*BB + b)*NG;                \
        _Pragma("unroll")                                                 \
        for (int i_=0;i_<3;i_++){                                         \
            int c_ = tid + i_*512;                                        \
            if (c_ < 256)       cpa16(sbase + PF_OFF + c_*16, xr_ + c_*4);\
            else if (c_ < 1280) cpa16(sbase + PF_OFF + 8192 + (c_-256)*16,\
                                      Zr_ + (c_-256)*4);                  \
        }                                                                 \
    } while(0)

    // pre-loop: x/Z for t=0
    PF_XZ(0);
    CP_COMMIT;

    for (int t = 0; t < TT; t++){
        // ======== GEMM phase: 3-stage pipeline, ONE sync per slab ========
        float acc[2][4][4];
        #pragma unroll
        for (int i=0;i<2;i++)
            #pragma unroll
            for (int j=0;j<4;j++)
                #pragma unroll
                for (int q=0;q<4;q++) acc[i][j][q] = 0.f;

        LOAD_A(0, 0); CP_COMMIT;   // group: slab0 (x/Z already in-flight)
        LOAD_A(1, 1); CP_COMMIT;   // group: slab1
        for (int s = 0; s < 8; s++){
            if (s < 7) CP_WAIT1; else CP_WAIT0;   // slab s resident
            __syncthreads();                       // all warps see stage s%3
            if (s + 2 < 8){ LOAD_A((s+2)%3, s+2); CP_COMMIT; }

            const uint32_t sA  = sAbase + (s%3)*16384;
            const uint32_t sBh = sbase + s*8192;
            #pragma unroll
            for (int kk = 0; kk < 2; kk++){
                uint32_t ah[2][4], al[2][4], bh[2][4], bl[2][4];
                #pragma unroll
                for (int mt=0; mt<2; mt++){
                    int r = wm*32 + mt*16 + (lane & 15);
                    int c = kk*2 + (lane >> 4);
                    uint32_t ad = sA + r*64 + (((c ^ ((r>>1)&3)))<<4);
                    ldsm4(ah[mt][0], ah[mt][1], ah[mt][2], ah[mt][3], ad);
                    ldsm4(al[mt][0], al[mt][1], al[mt][2], al[mt][3], ad + 8192);
                }
                #pragma unroll
                for (int ntp=0; ntp<2; ntp++){
                    int q = lane >> 3;
                    int n = wn*32 + ntp*16 + ((q>>1)<<3) + (lane & 7);
                    int kc = kk*2 + (q & 1);
                    uint32_t bd = sBh + n*64 + (((kc ^ ((n>>1)&3)))<<4);
                    ldsm4(bh[ntp][0], bh[ntp][1], bh[ntp][2], bh[ntp][3], bd);
                    ldsm4(bl[ntp][0], bl[ntp][1], bl[ntp][2], bl[ntp][3], bd + 65536);
                }
                // term-ordered issue: accumulator reuse distance = 8 MMAs
                #pragma unroll
                for (int mt=0; mt<2; mt++)
                    #pragma unroll
                    for (int ntp=0; ntp<2; ntp++){
                        mma16816(acc[mt][2*ntp],   ah[mt], bh[ntp]);
                        mma16816(acc[mt][2*ntp+1], ah[mt], bh[ntp]+2);
                    }
                #pragma unroll
                for (int mt=0; mt<2; mt++)
                    #pragma unroll
                    for (int ntp=0; ntp<2; ntp++){
                        mma16816(acc[mt][2*ntp],   ah[mt], bl[ntp]);
                        mma16816(acc[mt][2*ntp+1], ah[mt], bl[ntp]+2);
                    }
                #pragma unroll
                for (int mt=0; mt<2; mt++)
                    #pragma unroll
                    for (int ntp=0; ntp<2; ntp++){
                        mma16816(acc[mt][2*ntp],   al[mt], bh[ntp]);
                        mma16816(acc[mt][2*ntp+1], al[mt], bh[ntp]+2);
                    }
            }
            // no end-of-iteration sync: 3-stage rotation makes it redundant
        }

        // epilogue: write partials (L2-direct)
        #pragma unroll
        for (int mt=0; mt<2; mt++){
            int m = wm*32 + mt*16 + (lane >> 2);
            #pragma unroll
            for (int j=0; j<4; j++){
                int nc = wn*32 + j*8 + (lane & 3)*2;
                __stcg((float2*)(Pout + (size_t)m*NG + nc),
                       make_float2(acc[mt][j][0], acc[mt][j][1]));
                __stcg((float2*)(Pout + (size_t)(m+8)*NG + nc),
                       make_float2(acc[mt][j][2], acc[mt][j][3]));
            }
        }

        // ---- RBF partial BEFORE barrier A (uses only prefetched smem) ----
        {
            const int n2 = 2*tid;
            float2 xv = *(const float2*)(xsp + n2);
            float2 hv = *(const float2*)(hpsp + n2);
            float d0 = xv.x - hv.x, d1 = xv.y - hv.y;
            float sacc = d0*d0 + d1*d1;
            #pragma unroll
            for (int o=16;o;o>>=1) sacc += __shfl_xor_sync(0xFFFFFFFFu, sacc, o);
            if (lane == 0) red[wid] = sacc;
        }

        // ---- grid barrier A (single counter; also publishes red[]) ----
        __syncthreads();
        if (tid == 0){
            __threadfence();
            atomicAdd(&g_barcnt, 1u);
            unsigned tgt = 128u*(2u*t + 1u);
            while (*(volatile unsigned*)&g_barcnt < tgt) {}
        }
        __syncthreads();

        // ======== elementwise phase: batch row b, units 2*tid, 2*tid+1 ========
        {
            const int n2 = 2*tid;
            float tot = 0.f;
            #pragma unroll
            for (int w=0; w<16; w++) tot += red[w];
            const float kk_ = __expf(-tot);

            float2 pf = *(const float2*)(Zsp + n2);
            float2 pi = *(const float2*)(Zsp + 1024 + n2);
            float2 pu = *(const float2*)(Zsp + 2048 + n2);
            float2 po = *(const float2*)(Zsp + 3072 + n2);
            #pragma unroll
            for (int sp=0; sp<KSPLIT; sp++){
                const float* P = g_P + ((size_t)sp*BB + b)*NG;
                float2 a0 = __ldcg((const float2*)(P + n2));
                float2 a1 = __ldcg((const float2*)(P + 1024 + n2));
                float2 a2 = __ldcg((const float2*)(P + 2048 + n2));
                float2 a3 = __ldcg((const float2*)(P + 3072 + n2));
                pf.x += a0.x; pf.y += a0.y;
                pi.x += a1.x; pi.y += a1.y;
                pu.x += a2.x; pu.y += a2.y;
                po.x += a3.x; po.y += a3.y;
            }
            float f0 = fsig(pf.x + kk_), f1 = fsig(pf.y + kk_);
            float i0 = fsig(pi.x + kk_), i1 = fsig(pi.y + kk_);
            float u0 = ftanh(pu.x),      u1 = ftanh(pu.y);
            float o0 = fsig(po.x + kk_), o1 = fsig(po.y + kk_);
            creg.x = f0*creg.x + i0*u0;
            creg.y = f1*creg.y + i1*u1;
            float h0 = o0*ftanh(creg.x);
            float h1 = o1*ftanh(creg.y);
            *(float2*)(out + ((size_t)t*BB + b)*HH + n2) = make_float2(h0, h1);
            // hp for next step's RBF: own row, direct STS (no global round-trip)
            *(float2*)(smem + PF_OFF + 4096 + tid*8) = make_float2(h0, h1);
            __nv_bfloat16 hh0 = __float2bfloat16(h0);
            __nv_bfloat16 hh1 = __float2bfloat16(h1);
            union { __nv_bfloat16 bb[2]; uint32_t u; } HI, LO;
            HI.bb[0] = hh0; HI.bb[1] = hh1;
            LO.bb[0] = __float2bfloat16(h0 - __bfloat162float(hh0));
            LO.bb[1] = __float2bfloat16(h1 - __bfloat162float(hh1));
            *(uint32_t*)(g_hhi + b*HH + n2) = HI.u;
            *(uint32_t*)(g_hlo + b*HH + n2) = LO.u;
            if (t == TT-1){
                *(float2*)(out + (size_t)TT*BH + (size_t)b*HH + n2) = make_float2(h0, h1);
                *(float2*)(out + (size_t)TT*BH + BH + (size_t)b*HH + n2) = creg;
            }
        }

        // ---- grid barrier B (skipped after the final step): arrival, then
        //      x/Z prefetch for t+1 issued INSIDE the spin window ----
        if (t + 1 < TT){
            __syncthreads();
            if (tid == 0){
                __threadfence();
                atomicAdd(&g_barcnt, 1u);
            }
            PF_XZ(t + 1);
            CP_COMMIT;
            if (tid == 0){
                unsigned tgt = 128u*(2u*t + 2u);
                while (*(volatile unsigned*)&g_barcnt < tgt) {}
            }
            __syncthreads();
        }
    }
    #undef LOAD_A
    #undef PF_XZ
}

// ---------------- launch ----------------
#define SMEM_PRE  98304
#define SMEM_LOOP 204800

extern "C" void kernel_launch(void* const* d_in, const int* in_sizes, int n_in,
                              void* d_out, int out_size)
{
    const float* X   = (const float*)d_in[0];
    const float* Wf  = (const float*)d_in[1];
    const float* bfp = (const float*)d_in[2];
    const float* Wi  = (const float*)d_in[3];
    const float* bip = (const float*)d_in[4];
    const float* Wu  = (const float*)d_in[5];
    const float* bup = (const float*)d_in[6];
    const float* Wo  = (const float*)d_in[7];
    const float* bop = (const float*)d_in[8];
    float* out = (float*)d_out;

    cudaFuncSetAttribute(k_pre,  cudaFuncAttributeMaxDynamicSharedMemorySize, SMEM_PRE);
    cudaFuncSetAttribute(k_loop, cudaFuncAttributeMaxDynamicSharedMemorySize, SMEM_LOOP);

    k_init<<<BH/256, 256>>>(bfp, bip, bup, bop);
    k_cvtX<<<32768, 256>>>(X);
    k_cvtW<<<dim3(1024, 4), 256>>>(Wf, Wi, Wu, Wo);
    k_pre<<<dim3(32, 256), 256, SMEM_PRE>>>();
    k_loop<<<128, 512, SMEM_LOOP>>>(X, out);
}